// round 6
// baseline (speedup 1.0000x reference)
#include <cuda_runtime.h>
#include <cstdint>

#define NB 32768
#define NT 64

typedef unsigned long long u64;

__device__ int g_idx[NB];

// ---- f32x2 packed helpers (sm_100+), .b64 regs ----
__device__ __forceinline__ u64 pk2(float a, float b) {
    u64 d; asm("mov.b64 %0, {%1, %2};" : "=l"(d) : "f"(a), "f"(b)); return d;
}
__device__ __forceinline__ void upk2(u64 d, float& a, float& b) {
    asm("mov.b64 {%0, %1}, %2;" : "=f"(a), "=f"(b) : "l"(d));
}
__device__ __forceinline__ void fma2(u64& acc, u64 a, u64 b) {
    asm("fma.rn.f32x2 %0, %1, %2, %3;" : "=l"(acc) : "l"(a), "l"(b), "l"(acc));
}
__device__ __forceinline__ void lds2(uint32_t addr, u64& a, u64& b) {
    asm volatile("ld.shared.v2.b64 {%0, %1}, [%2];" : "=l"(a), "=l"(b) : "r"(addr));
}
__device__ __forceinline__ float lds32f(uint32_t addr) {
    float f; asm volatile("ld.shared.f32 %0, [%1];" : "=f"(f) : "r"(addr)); return f;
}
__device__ __forceinline__ void sts32f(uint32_t addr, float v) {
    asm volatile("st.shared.f32 [%0], %1;" :: "r"(addr), "f"(v) : "memory");
}
__device__ __forceinline__ float rcpa(float x) {
    float r; asm("rcp.approx.ftz.f32 %0, %1;" : "=f"(r) : "f"(x)); return r;
}
__device__ __forceinline__ float hadd(u64 d) {
    float a, b; upk2(d, a, b); return a + b;
}
__device__ __forceinline__ float tanhfast(float x) {
    float e = __expf(-2.f * x);
    return __fdividef(2.f, 1.f + e) - 1.f;
}

struct SmemGRU {
    float Whh[192][68];     // 272B stride: conflict-free LDS.128, 16B aligned
    float Whd[4][64];
    float bhd[4];
    float H[2][2][8][64];   // [group][buf][sample][k]; 256B rows
};

// 2048 CTAs x 128 threads. Warp-pair (2 warps) owns one 8-sample group;
// each lane owns ONE hidden unit (ug = (w&1)*32 + lane). k-SIMD f32x2:
// weight and h pairs load directly as u64 -> no splat MOVs.
__global__ void __launch_bounds__(128, 3) gru_sel_kernel(
    const float* __restrict__ Hn,
    const float* __restrict__ gum,
    const float* __restrict__ Wih,
    const float* __restrict__ Whh,
    const float* __restrict__ bih,
    const float* __restrict__ bhh,
    const float* __restrict__ Whead,
    const float* __restrict__ bhead,
    float* __restrict__ out)
{
    extern __shared__ char smem_raw[];
    SmemGRU& S = *reinterpret_cast<SmemGRU*>(smem_raw);
    const int tid = threadIdx.x;

    for (int i = tid; i < 192 * 64; i += 128) S.Whh[i >> 6][i & 63] = Whh[i];
    for (int i = tid; i < 256; i += 128) S.Whd[i >> 6][i & 63] = Whead[i];
    if (tid < 4) S.bhd[tid] = bhead[tid];
    for (int i = tid; i < 2 * 2 * 8 * 64; i += 128) (&S.H[0][0][0][0])[i] = 0.f;
    __syncthreads();

    const int w = tid >> 5, lane = tid & 31;
    const int g = w >> 1, wh = w & 1;
    const int ug = wh * 32 + lane;           // this lane's hidden unit
    const int b0 = (blockIdx.x * 2 + g) * 8; // group's first sample
    const float* hp = Hn + (size_t)b0 * (NT * 4);
    const int barid = 1 + g;

    // SMEM addresses
    const uint32_t WhhA = (uint32_t)__cvta_generic_to_shared(&S.Whh[ug][0]);
    const uint32_t WhhB = (uint32_t)__cvta_generic_to_shared(&S.Whh[ug + 64][0]);
    const uint32_t WhhC = (uint32_t)__cvta_generic_to_shared(&S.Whh[ug + 128][0]);
    uint32_t HR = (uint32_t)__cvta_generic_to_shared(&S.H[g][0][0][0]);
    uint32_t HW = (uint32_t)__cvta_generic_to_shared(&S.H[g][1][0][0]);

    // biases (registers)
    const float br  = __ldg(&bih[ug])       + __ldg(&bhh[ug]);
    const float bz  = __ldg(&bih[64 + ug])  + __ldg(&bhh[64 + ug]);
    const float bin = __ldg(&bih[128 + ug]);
    const float bhn = __ldg(&bhh[128 + ug]);

    // W_ih rows (t-invariant, registers, already k-paired)
    u64 wiR0, wiR1, wiZ0, wiZ1, wiN0, wiN1;
    { float4 f = __ldg((const float4*)(Wih + (size_t)ug * 4));
      wiR0 = pk2(f.x, f.y); wiR1 = pk2(f.z, f.w); }
    { float4 f = __ldg((const float4*)(Wih + (size_t)(64 + ug) * 4));
      wiZ0 = pk2(f.x, f.y); wiZ1 = pk2(f.z, f.w); }
    { float4 f = __ldg((const float4*)(Wih + (size_t)(128 + ug) * 4));
      wiN0 = pk2(f.x, f.y); wiN1 = pk2(f.z, f.w); }

    u64 accR[8], accZ[8], accN[8];
    float ains[8];

#pragma unroll 1
    for (int t = 0; t < NT; t++) {
        // ---- input phase (independent of H) ----
#pragma unroll
        for (int s = 0; s < 8; s++) {
            const float4 x = __ldg((const float4*)(hp + ((size_t)s * NT + t) * 4));
            const u64 x01 = pk2(x.x, x.y), x23 = pk2(x.z, x.w);
            u64 aR = 0ull; fma2(aR, wiR0, x01); fma2(aR, wiR1, x23); accR[s] = aR;
            u64 aZ = 0ull; fma2(aZ, wiZ0, x01); fma2(aZ, wiZ1, x23); accZ[s] = aZ;
            u64 aN = 0ull; fma2(aN, wiN0, x01); fma2(aN, wiN1, x23);
            ains[s] = hadd(aN) + bin;
            accN[s] = 0ull;
        }
        // ---- recurrence: 3 gate rows x 64-dot, k-pair SIMD; weights amortized over 8 samples ----
#pragma unroll 4
        for (int kc = 0; kc < 64; kc += 4) {
            u64 wra, wrb, wza, wzb, wna, wnb;
            lds2(WhhA + kc * 4, wra, wrb);
            lds2(WhhB + kc * 4, wza, wzb);
            lds2(WhhC + kc * 4, wna, wnb);
#pragma unroll
            for (int s = 0; s < 8; s++) {
                u64 h01, h23;
                lds2(HR + (s * 64 + kc) * 4, h01, h23);   // broadcast
                fma2(accR[s], wra, h01); fma2(accR[s], wrb, h23);
                fma2(accZ[s], wza, h01); fma2(accZ[s], wzb, h23);
                fma2(accN[s], wna, h01); fma2(accN[s], wnb, h23);
            }
        }
        // ---- activations: horizontal add + paired-rcp sigmoids ----
#pragma unroll
        for (int s = 0; s < 8; s++) {
            const float dr = hadd(accR[s]) + br;
            const float dz = hadd(accZ[s]) + bz;
            const float dn = hadd(accN[s]) + bhn;
            const float er = __expf(-dr), ez = __expf(-dz);
            const float A = 1.f + er, B = 1.f + ez;
            const float ip = rcpa(A * B);          // one rcp serves both sigmoids
            const float r  = B * ip;               // sigmoid(dr)
            const float zv = A * ip;               // sigmoid(dz)
            const float targ = ains[s] + r * dn;
            const float et = __expf(-2.f * targ);
            const float n  = fmaf(2.f, rcpa(1.f + et), -1.f);   // tanh
            const float ho = lds32f(HR + (s * 64 + ug) * 4);
            sts32f(HW + (s * 64 + ug) * 4, n + zv * (ho - n));
        }
        asm volatile("bar.sync %0, 64;" :: "r"(barid) : "memory");
        const uint32_t tmp = HR; HR = HW; HW = tmp;
    }

    // ---- head + gumbel argmax: only warp A of each pair; final h in buf 0 ----
    if (wh == 0) {
        const int sl = lane >> 2, ml = lane & 3;
        float acc = S.bhd[ml];
#pragma unroll
        for (int k = 0; k < 64; k += 4) {
            const float4 wv = *(const float4*)&S.Whd[ml][k];
            const float4 h4 = *(const float4*)&S.H[g][0][sl][k];
            acc += wv.x * h4.x + wv.y * h4.y + wv.z * h4.z + wv.w * h4.w;
        }
        const int b = b0 + sl;
        const float lv = acc + __ldg(&gum[b * 4 + ml]);
        float best = lv;
        int   bi   = ml;
#pragma unroll
        for (int d = 1; d < 4; d <<= 1) {
            const float ob = __shfl_xor_sync(0xffffffffu, best, d);
            const int   oi = __shfl_xor_sync(0xffffffffu, bi, d);
            if (ob > best || (ob == best && oi < bi)) { best = ob; bi = oi; }
        }
        out[131072 + b * 4 + ml] = acc;                       // logits
        out[262144 + b * 4 + ml] = (ml == bi) ? 1.f : 0.f;    // onehot
        if (ml == 0) { out[393216 + b] = (float)bi; g_idx[b] = bi; }
    }
}

// Expert bank: unchanged (35us, not the bottleneck).
__global__ void __launch_bounds__(256) bank_kernel(
    const float* __restrict__ Xp,
    const float* __restrict__ dtp,
    const float* __restrict__ W1,
    const float* __restrict__ b1,
    const float* __restrict__ W2,
    const float* __restrict__ b2,
    float* __restrict__ out)
{
    __shared__ float sW1[4 * 5 * 256];
    __shared__ float sb1[4 * 256];
    __shared__ float sW2[4][256][5];
    __shared__ float sb2[16];
    const int tid = threadIdx.x;
    for (int i = tid; i < 5120; i += 256) sW1[i] = W1[i];
    for (int i = tid; i < 1024; i += 256) sb1[i] = b1[i];
    for (int i = tid; i < 4096; i += 256) sW2[i >> 10][(i >> 2) & 255][i & 3] = W2[i];
    if (tid < 16) sb2[tid] = b2[tid];
    __syncthreads();

    const float dt = __ldg(dtp);
    const int gw = blockIdx.x * 8 + (tid >> 5);
    const int lane = tid & 31;
#pragma unroll 1
    for (int it = 0; it < 8; it++) {
        const int b = gw * 8 + it;
        const int e = g_idx[b];
        const float4 xv = __ldg((const float4*)(Xp + b * 4));
        const float* w1e = sW1 + e * 1280;
        float hid[8];
#pragma unroll
        for (int j = 0; j < 8; j++) {
            const int u = lane + 32 * j;
            float a = sb1[e * 256 + u]
                    + xv.x * w1e[0 * 256 + u]
                    + xv.y * w1e[1 * 256 + u]
                    + xv.z * w1e[2 * 256 + u]
                    + xv.w * w1e[3 * 256 + u]
                    + dt   * w1e[4 * 256 + u];
            hid[j] = tanhfast(a);
        }
        float f0 = 0.f, f1 = 0.f, f2 = 0.f, f3 = 0.f;
#pragma unroll
        for (int j = 0; j < 8; j++) {
            const int u = lane + 32 * j;
            f0 += hid[j] * sW2[e][u][0];
            f1 += hid[j] * sW2[e][u][1];
            f2 += hid[j] * sW2[e][u][2];
            f3 += hid[j] * sW2[e][u][3];
        }
#pragma unroll
        for (int off = 16; off >= 1; off >>= 1) {
            f0 += __shfl_xor_sync(0xffffffffu, f0, off);
            f1 += __shfl_xor_sync(0xffffffffu, f1, off);
            f2 += __shfl_xor_sync(0xffffffffu, f2, off);
            f3 += __shfl_xor_sync(0xffffffffu, f3, off);
        }
        if (lane < 4) {
            float fv = (lane == 0) ? f0 : (lane == 1) ? f1 : (lane == 2) ? f2 : f3;
            fv += sb2[e * 4 + lane];
            out[b * 4 + lane] = __ldg(&Xp[b * 4 + lane]) + dt * fv;
        }
    }
}

extern "C" void kernel_launch(void* const* d_in, const int* in_sizes, int n_in,
                              void* d_out, int out_size) {
    const float* Hn    = (const float*)d_in[0];
    const float* Xp    = (const float*)d_in[1];
    const float* dtp   = (const float*)d_in[2];
    const float* gum   = (const float*)d_in[3];
    const float* Wih   = (const float*)d_in[4];
    const float* Whh   = (const float*)d_in[5];
    const float* bih   = (const float*)d_in[6];
    const float* bhh   = (const float*)d_in[7];
    const float* Whead = (const float*)d_in[8];
    const float* bhead = (const float*)d_in[9];
    const float* W1    = (const float*)d_in[10];
    const float* b1    = (const float*)d_in[11];
    const float* W2    = (const float*)d_in[12];
    const float* b2    = (const float*)d_in[13];
    float* out = (float*)d_out;

    const int smem = (int)sizeof(SmemGRU);   // ~61.5 KB
    cudaFuncSetAttribute(gru_sel_kernel, cudaFuncAttributeMaxDynamicSharedMemorySize, smem);

    gru_sel_kernel<<<2048, 128, smem>>>(Hn, gum, Wih, Whh, bih, bhh, Whead, bhead, out);
    bank_kernel<<<512, 256>>>(Xp, dtp, W1, b1, W2, b2, out);
}

// round 7
// speedup vs baseline: 1.0856x; 1.0856x over previous
#include <cuda_runtime.h>
#include <cstdint>

#define NB 32768
#define NT 64

typedef unsigned long long u64;

__device__ int g_idx[NB];

// ---- f32x2 packed helpers (sm_100+), .b64 regs ----
__device__ __forceinline__ u64 splat2(float w) {
    u64 d; asm("mov.b64 %0, {%1, %1};" : "=l"(d) : "f"(w)); return d;
}
__device__ __forceinline__ u64 pk2(float a, float b) {
    u64 d; asm("mov.b64 %0, {%1, %2};" : "=l"(d) : "f"(a), "f"(b)); return d;
}
__device__ __forceinline__ void upk2(u64 d, float& a, float& b) {
    asm("mov.b64 {%0, %1}, %2;" : "=f"(a), "=f"(b) : "l"(d));
}
__device__ __forceinline__ void fma2(u64& acc, u64 a, u64 b) {
    asm("fma.rn.f32x2 %0, %1, %2, %3;" : "=l"(acc) : "l"(a), "l"(b), "l"(acc));
}
__device__ __forceinline__ void lds2(uint32_t addr, u64& a, u64& b) {
    asm volatile("ld.shared.v2.b64 {%0, %1}, [%2];" : "=l"(a), "=l"(b) : "r"(addr));
}
__device__ __forceinline__ void sts128(uint32_t addr, float a, float b, float c, float d) {
    asm volatile("st.shared.v4.f32 [%0], {%1, %2, %3, %4};"
                 :: "r"(addr), "f"(a), "f"(b), "f"(c), "f"(d) : "memory");
}
__device__ __forceinline__ float rcpa(float x) {
    float r; asm("rcp.approx.ftz.f32 %0, %1;" : "=f"(r) : "f"(x)); return r;
}
__device__ __forceinline__ float tanhfast(float x) {
    float e = __expf(-2.f * x);
    return __fdividef(2.f, 1.f + e) - 1.f;
}

struct SmemGRU {
    float Whh[192][68];   // 272B stride: conflict-free LDS.128
    float Whd[4][64];
    float bhd[4];
    float H[4][64][4];    // [warp][k][sample]; 16B rows -> one broadcast v2.b64 per k
};

// 2048 CTAs x 128 threads; each warp INDEPENDENTLY owns 4 samples (2 f32x2 pairs).
// Lane owns units u0=lane, u1=lane+32 (gate rows u, u+64, u+128). No inter-warp sync.
__global__ void __launch_bounds__(128, 3) gru_sel_kernel(
    const float* __restrict__ Hn,
    const float* __restrict__ gum,
    const float* __restrict__ Wih,
    const float* __restrict__ Whh,
    const float* __restrict__ bih,
    const float* __restrict__ bhh,
    const float* __restrict__ Whead,
    const float* __restrict__ bhead,
    float* __restrict__ out)
{
    extern __shared__ char smem_raw[];
    SmemGRU& S = *reinterpret_cast<SmemGRU*>(smem_raw);
    const int tid = threadIdx.x;

    for (int i = tid; i < 192 * 64; i += 128) S.Whh[i >> 6][i & 63] = Whh[i];
    for (int i = tid; i < 256; i += 128) S.Whd[i >> 6][i & 63] = Whead[i];
    if (tid < 4) S.bhd[tid] = bhead[tid];
    for (int i = tid; i < 4 * 64 * 4; i += 128) (&S.H[0][0][0])[i] = 0.f;
    __syncthreads();

    const int w = tid >> 5, lane = tid & 31;
    const int u0 = lane, u1 = lane + 32;
    const int b0 = (blockIdx.x * 4 + w) * 4;        // warp's 4 samples
    const float* hp = Hn + (size_t)b0 * (NT * 4);

    const uint32_t HR = (uint32_t)__cvta_generic_to_shared(&S.H[w][0][0]);

    // biases (registers)
    const float br0f = __ldg(&bih[u0])       + __ldg(&bhh[u0]);
    const float bz0f = __ldg(&bih[64 + u0])  + __ldg(&bhh[64 + u0]);
    const float bi0f = __ldg(&bih[128 + u0]);
    const float bh0f = __ldg(&bhh[128 + u0]);
    const float br1f = __ldg(&bih[u1])       + __ldg(&bhh[u1]);
    const float bz1f = __ldg(&bih[64 + u1])  + __ldg(&bhh[64 + u1]);
    const float bi1f = __ldg(&bih[128 + u1]);
    const float bh1f = __ldg(&bhh[128 + u1]);
    const u64 br0 = splat2(br0f), bz0 = splat2(bz0f), bi0 = splat2(bi0f), bh0 = splat2(bh0f);
    const u64 br1 = splat2(br1f), bz1 = splat2(bz1f), bi1 = splat2(bi1f), bh1 = splat2(bh1f);

    // W_ih rows (t-invariant, registers)
    const float4 wiR0 = __ldg((const float4*)(Wih + (size_t)u0 * 4));
    const float4 wiZ0 = __ldg((const float4*)(Wih + (size_t)(64 + u0) * 4));
    const float4 wiN0 = __ldg((const float4*)(Wih + (size_t)(128 + u0) * 4));
    const float4 wiR1 = __ldg((const float4*)(Wih + (size_t)u1 * 4));
    const float4 wiZ1 = __ldg((const float4*)(Wih + (size_t)(64 + u1) * 4));
    const float4 wiN1 = __ldg((const float4*)(Wih + (size_t)(128 + u1) * 4));

    u64 ar[2][2], az[2][2], ahn[2][2], ain[2][2];
    float hreg[2][4] = {{0.f, 0.f, 0.f, 0.f}, {0.f, 0.f, 0.f, 0.f}};

#pragma unroll 1
    for (int t = 0; t < NT; t++) {
        // ---- input phase (independent of H) ----
        u64 xp[4][2];   // [k][sp]
#pragma unroll
        for (int sp = 0; sp < 2; sp++) {
            const float4 xa = __ldg((const float4*)(hp + ((size_t)(2 * sp)     * NT + t) * 4));
            const float4 xb = __ldg((const float4*)(hp + ((size_t)(2 * sp + 1) * NT + t) * 4));
            xp[0][sp] = pk2(xa.x, xb.x);
            xp[1][sp] = pk2(xa.y, xb.y);
            xp[2][sp] = pk2(xa.z, xb.z);
            xp[3][sp] = pk2(xa.w, xb.w);
        }
#define IROW(W4, ACC, BIAS)                                               \
        {   const u64 s0 = splat2((W4).x), s1 = splat2((W4).y),           \
                      s2 = splat2((W4).z), s3 = splat2((W4).w);           \
            _Pragma("unroll")                                             \
            for (int sp = 0; sp < 2; sp++) {                              \
                ACC[sp] = BIAS;                                           \
                fma2(ACC[sp], s0, xp[0][sp]);                             \
                fma2(ACC[sp], s1, xp[1][sp]);                             \
                fma2(ACC[sp], s2, xp[2][sp]);                             \
                fma2(ACC[sp], s3, xp[3][sp]);                             \
            } }
        IROW(wiR0, ar[0], br0)  IROW(wiZ0, az[0], bz0)  IROW(wiN0, ain[0], bi0)
        IROW(wiR1, ar[1], br1)  IROW(wiZ1, az[1], bz1)  IROW(wiN1, ain[1], bi1)
#pragma unroll
        for (int sp = 0; sp < 2; sp++) { ahn[0][sp] = bh0; ahn[1][sp] = bh1; }

        // ---- recurrence: 6 gate rows x 64-dot; one broadcast v2.b64 per k ----
#pragma unroll 4
        for (int kc = 0; kc < 64; kc += 4) {
            u64 hk[4][2];   // [k][sp]
#pragma unroll
            for (int k = 0; k < 4; k++)
                lds2(HR + (kc + k) * 16, hk[k][0], hk[k][1]);
#define RROW(ROW, ACC)                                                    \
            {   const float4 w4 = *(const float4*)&S.Whh[ROW][kc];        \
                const u64 s0 = splat2(w4.x), s1 = splat2(w4.y),           \
                          s2 = splat2(w4.z), s3 = splat2(w4.w);           \
                _Pragma("unroll")                                         \
                for (int sp = 0; sp < 2; sp++) {                          \
                    fma2(ACC[sp], s0, hk[0][sp]);                         \
                    fma2(ACC[sp], s1, hk[1][sp]);                         \
                    fma2(ACC[sp], s2, hk[2][sp]);                         \
                    fma2(ACC[sp], s3, hk[3][sp]);                         \
                } }
            RROW(u0,       ar[0])
            RROW(u0 + 64,  az[0])
            RROW(u0 + 128, ahn[0])
            RROW(u1,       ar[1])
            RROW(u1 + 64,  az[1])
            RROW(u1 + 128, ahn[1])
        }
        __syncwarp();   // all lanes done reading old H

        // ---- activations: paired-rcp sigmoids; own h kept in registers ----
#pragma unroll
        for (int un = 0; un < 2; un++) {
#pragma unroll
            for (int sp = 0; sp < 2; sp++) {
                float dra, drb, dza, dzb, dia, dib, dna, dnb;
                upk2(ar[un][sp],  dra, drb);
                upk2(az[un][sp],  dza, dzb);
                upk2(ain[un][sp], dia, dib);
                upk2(ahn[un][sp], dna, dnb);
#pragma unroll
                for (int h = 0; h < 2; h++) {
                    const float dr = h ? drb : dra;
                    const float dz = h ? dzb : dza;
                    const float di = h ? dib : dia;
                    const float dn = h ? dnb : dna;
                    const int s = 2 * sp + h;
                    const float er = __expf(-dr), ez = __expf(-dz);
                    const float A = 1.f + er, B = 1.f + ez;
                    const float ip = rcpa(A * B);     // shared rcp for both sigmoids
                    const float r  = B * ip;          // sigmoid(dr)
                    const float zv = A * ip;          // sigmoid(dz)
                    const float et = __expf(-2.f * (di + r * dn));
                    const float n  = fmaf(2.f, rcpa(1.f + et), -1.f);   // tanh
                    hreg[un][s] = n + zv * (hreg[un][s] - n);
                }
            }
        }
        sts128(HR + u0 * 16, hreg[0][0], hreg[0][1], hreg[0][2], hreg[0][3]);
        sts128(HR + u1 * 16, hreg[1][0], hreg[1][1], hreg[1][2], hreg[1][3]);
        __syncwarp();   // new h visible to all lanes
    }

    // ---- head + gumbel argmax: lanes 0..15 -> (sample = lane>>2, mode = lane&3) ----
    if (lane < 16) {
        const int sl = lane >> 2, ml = lane & 3;
        float acc = S.bhd[ml];
#pragma unroll
        for (int k = 0; k < 64; k++)
            acc += S.Whd[ml][k] * S.H[w][k][sl];
        const int b = b0 + sl;
        const float lv = acc + __ldg(&gum[b * 4 + ml]);
        float best = lv;
        int   bi   = ml;
#pragma unroll
        for (int d = 1; d < 4; d <<= 1) {
            const float ob = __shfl_xor_sync(0x0000ffffu, best, d);
            const int   oi = __shfl_xor_sync(0x0000ffffu, bi, d);
            if (ob > best || (ob == best && oi < bi)) { best = ob; bi = oi; }
        }
        out[131072 + b * 4 + ml] = acc;                       // logits
        out[262144 + b * 4 + ml] = (ml == bi) ? 1.f : 0.f;    // onehot
        if (ml == 0) { out[393216 + b] = (float)bi; g_idx[b] = bi; }
    }
}

// Expert bank: unchanged (35us, not the bottleneck).
__global__ void __launch_bounds__(256) bank_kernel(
    const float* __restrict__ Xp,
    const float* __restrict__ dtp,
    const float* __restrict__ W1,
    const float* __restrict__ b1,
    const float* __restrict__ W2,
    const float* __restrict__ b2,
    float* __restrict__ out)
{
    __shared__ float sW1[4 * 5 * 256];
    __shared__ float sb1[4 * 256];
    __shared__ float sW2[4][256][5];
    __shared__ float sb2[16];
    const int tid = threadIdx.x;
    for (int i = tid; i < 5120; i += 256) sW1[i] = W1[i];
    for (int i = tid; i < 1024; i += 256) sb1[i] = b1[i];
    for (int i = tid; i < 4096; i += 256) sW2[i >> 10][(i >> 2) & 255][i & 3] = W2[i];
    if (tid < 16) sb2[tid] = b2[tid];
    __syncthreads();

    const float dt = __ldg(dtp);
    const int gw = blockIdx.x * 8 + (tid >> 5);
    const int lane = tid & 31;
#pragma unroll 1
    for (int it = 0; it < 8; it++) {
        const int b = gw * 8 + it;
        const int e = g_idx[b];
        const float4 xv = __ldg((const float4*)(Xp + b * 4));
        const float* w1e = sW1 + e * 1280;
        float hid[8];
#pragma unroll
        for (int j = 0; j < 8; j++) {
            const int u = lane + 32 * j;
            float a = sb1[e * 256 + u]
                    + xv.x * w1e[0 * 256 + u]
                    + xv.y * w1e[1 * 256 + u]
                    + xv.z * w1e[2 * 256 + u]
                    + xv.w * w1e[3 * 256 + u]
                    + dt   * w1e[4 * 256 + u];
            hid[j] = tanhfast(a);
        }
        float f0 = 0.f, f1 = 0.f, f2 = 0.f, f3 = 0.f;
#pragma unroll
        for (int j = 0; j < 8; j++) {
            const int u = lane + 32 * j;
            f0 += hid[j] * sW2[e][u][0];
            f1 += hid[j] * sW2[e][u][1];
            f2 += hid[j] * sW2[e][u][2];
            f3 += hid[j] * sW2[e][u][3];
        }
#pragma unroll
        for (int off = 16; off >= 1; off >>= 1) {
            f0 += __shfl_xor_sync(0xffffffffu, f0, off);
            f1 += __shfl_xor_sync(0xffffffffu, f1, off);
            f2 += __shfl_xor_sync(0xffffffffu, f2, off);
            f3 += __shfl_xor_sync(0xffffffffu, f3, off);
        }
        if (lane < 4) {
            float fv = (lane == 0) ? f0 : (lane == 1) ? f1 : (lane == 2) ? f2 : f3;
            fv += sb2[e * 4 + lane];
            out[b * 4 + lane] = __ldg(&Xp[b * 4 + lane]) + dt * fv;
        }
    }
}

extern "C" void kernel_launch(void* const* d_in, const int* in_sizes, int n_in,
                              void* d_out, int out_size) {
    const float* Hn    = (const float*)d_in[0];
    const float* Xp    = (const float*)d_in[1];
    const float* dtp   = (const float*)d_in[2];
    const float* gum   = (const float*)d_in[3];
    const float* Wih   = (const float*)d_in[4];
    const float* Whh   = (const float*)d_in[5];
    const float* bih   = (const float*)d_in[6];
    const float* bhh   = (const float*)d_in[7];
    const float* Whead = (const float*)d_in[8];
    const float* bhead = (const float*)d_in[9];
    const float* W1    = (const float*)d_in[10];
    const float* b1    = (const float*)d_in[11];
    const float* W2    = (const float*)d_in[12];
    const float* b2    = (const float*)d_in[13];
    float* out = (float*)d_out;

    const int smem = (int)sizeof(SmemGRU);   // ~57.4 KB -> 3 CTAs/SM
    cudaFuncSetAttribute(gru_sel_kernel, cudaFuncAttributeMaxDynamicSharedMemorySize, smem);

    gru_sel_kernel<<<2048, 128, smem>>>(Hn, gum, Wih, Whh, bih, bhh, Whead, bhead, out);
    bank_kernel<<<512, 256>>>(Xp, dtp, W1, b1, W2, b2, out);
}